// round 9
// baseline (speedup 1.0000x reference)
#include <cuda_runtime.h>
#include <math.h>

// C=6, N=5 modes, LAYERS=4, OUTPUT=2, B=2048
#define DIM 7776            // 6^5
#define BD  256
typedef unsigned long long ull;

// packed gate coeff: a = (ur,ur), b = (ui,ui)
struct __align__(16) GU { ull a, b; };

// gate schedule: 8 half-layers x (10 BS(146) + 5 one-mode(36)) = 120 gates, 13120 GU
#define HLSZ 1640
#define NGATE 120
#define GOFF(k) (((k) / 15) * HLSZ + (((k) % 15) < 10 ? ((k) % 15) * 146 : (1460 + (((k) % 15) - 10) * 36)))
#define GSZ(k)  ((((k) % 15) < 10) ? 146 : 36)

// ---------------- persistent device scratch ----------------
__device__ GU    g_all[8 * HLSZ];    // all gates in execution order
__device__ float g_init[2048 * 5 * 6];

__constant__ float SQT[5] = {1.0f, 1.41421356237f, 1.73205080757f, 2.0f, 2.2360679775f};

// ---------------- helpers ----------------
__device__ __forceinline__ float2 cmul(float2 a, float2 b) {
    return make_float2(a.x * b.x - a.y * b.y, a.x * b.y + a.y * b.x);
}
__device__ __forceinline__ float2 cmadd(float2 a, float2 b, float2 c) {
    c.x = fmaf(a.x, b.x, fmaf(-a.y, b.y, c.x));
    c.y = fmaf(a.x, b.y, fmaf(a.y, b.x, c.y));
    return c;
}
__device__ __forceinline__ void ffma2(ull& d, ull a, ull b) {
    asm("fma.rn.f32x2 %0, %1, %2, %0;" : "+l"(d) : "l"(a), "l"(b));
}
__device__ __forceinline__ ull pack2(float v) {
    unsigned u = __float_as_uint(v);
    return ((ull)u << 32) | (ull)u;
}

// ---------------- banded 6x6 expm (registers), bands at +-D, pre-scaled 1/64 ----
template <int D>
__device__ void expm_banded(const float2* lo, const float2* hi, float2* R) {
    float2 T[36];
#pragma unroll
    for (int i = 0; i < 36; i++) R[i] = make_float2(((i % 6) == (i / 6)) ? 1.f : 0.f, 0.f);
#pragma unroll 1
    for (int k = 16; k >= 1; k--) {
#pragma unroll
        for (int i = 0; i < 6; i++) {
#pragma unroll
            for (int j = 0; j < 6; j++) {
                float2 acc = make_float2(0.f, 0.f);
                if (i >= D)    acc = cmadd(lo[i], R[(i - D) * 6 + j], acc);
                if (i + D < 6) acc = cmadd(hi[i], R[(i + D) * 6 + j], acc);
                T[i * 6 + j] = acc;
            }
        }
        float inv = 1.f / (float)k;
#pragma unroll
        for (int i = 0; i < 36; i++) {
            float d = ((i % 6) == (i / 6)) ? 1.f : 0.f;
            R[i] = make_float2(fmaf(T[i].x, inv, d), T[i].y * inv);
        }
    }
#pragma unroll 1
    for (int s = 0; s < 6; s++) {
#pragma unroll
        for (int i = 0; i < 6; i++)
#pragma unroll
            for (int j = 0; j < 6; j++) {
                float2 acc = make_float2(0.f, 0.f);
#pragma unroll
                for (int kk = 0; kk < 6; kk++) acc = cmadd(R[i * 6 + kk], R[kk * 6 + j], acc);
                T[i * 6 + j] = acc;
            }
#pragma unroll
        for (int i = 0; i < 36; i++) R[i] = T[i];
    }
}

// ---------------- dummy kernel (ncu launch-index alignment) ----------------
__global__ void noop_kernel() {}

// ---------------- S1: initial columns + 6x6 gates (rot + kerr folded) ----------
__global__ void s1_kernel(const float* __restrict__ x, const float* __restrict__ lin,
                          const float* __restrict__ act, const float* __restrict__ lact,
                          int B) {
    int idx = blockIdx.x * blockDim.x + threadIdx.x;
    int nInit = B * 5;
    const float sc = 1.f / 64.f;
    float2 lo[6], hi[6], R[36];
    if (idx < nInit) {
        float r = x[idx];   // disp(r, 0)
#pragma unroll
        for (int n = 0; n < 6; n++) {
            lo[n] = make_float2(r * sqrtf((float)n) * sc, 0.f);
            hi[n] = make_float2(-r * sqrtf((float)(n + 1)) * sc, 0.f);
        }
        expm_banded<1>(lo, hi, R);
#pragma unroll
        for (int n = 0; n < 6; n++) g_init[idx * 6 + n] = R[n * 6].x;  // column 0 (real)
    } else if (idx < nInit + 40) {
        int k = idx - nInit;
        int isDp = (k >= 20);
        int k2 = isDp ? k - 20 : k;
        int l = k2 / 5, i = k2 - 5 * l;
        float rphi;
        if (!isDp) {
            float r = lin[l * 63 + 24 + i];
#pragma unroll
            for (int n = 0; n < 6; n++) {
                lo[n] = make_float2(-0.5f * r * sqrtf((float)(n * (n - 1))) * sc, 0.f);
                hi[n] = make_float2( 0.5f * r * sqrtf((float)((n + 1) * (n + 2))) * sc, 0.f);
            }
            expm_banded<2>(lo, hi, R);
            rphi = (i < 4) ? lin[l * 63 + 20 + i] : 0.f;   // interferometer A rot
        } else {
            float dr = lin[l * 63 + 53 + i];
            float dp = lin[l * 63 + 58 + i];
            float sp, cp; sincosf(dp, &sp, &cp);
#pragma unroll
            for (int n = 0; n < 6; n++) {
                float sn = sqrtf((float)n) * sc, sn1 = sqrtf((float)(n + 1)) * sc;
                lo[n] = make_float2(dr * cp * sn, dr * sp * sn);
                hi[n] = make_float2(-dr * cp * sn1, dr * sp * sn1);
            }
            expm_banded<1>(lo, hi, R);
            rphi = (i < 4) ? lin[l * 63 + 49 + i] : 0.f;   // interferometer B rot
        }
        // fold rotation diagonal: column j *= e^{i rphi j}
#pragma unroll
        for (int c = 0; c < 6; c++) {
            float s2, c2; sincosf(rphi * (float)c, &s2, &c2);
            float2 ph = make_float2(c2, s2);
#pragma unroll
            for (int rr = 0; rr < 6; rr++) R[rr * 6 + c] = cmul(R[rr * 6 + c], ph);
        }
        if (isDp) {
            // fold kerr diagonal (applied right after disp on same mode): row r *= e^{i kv r^2}
            float kv = (l < 3) ? act[l * 5 + i] : ((i < 2) ? lact[i] : 0.f);
#pragma unroll
            for (int rr = 0; rr < 6; rr++) {
                float s2, c2; sincosf(kv * (float)(rr * rr), &s2, &c2);
                float2 ph = make_float2(c2, s2);
#pragma unroll
                for (int c = 0; c < 6; c++) R[rr * 6 + c] = cmul(ph, R[rr * 6 + c]);
            }
        }
        // layout: half 0 gets squeeze, half 1 gets disp
        int hl = 2 * l + (isDp ? 1 : 0);
        GU* dst = g_all + hl * HLSZ + 1460 + i * 36;
#pragma unroll
        for (int e = 0; e < 36; e++) dst[e] = GU{pack2(R[e].x), pack2(R[e].y)};
    }
}

// ---------------- S2: 80 beam-splitter 36x36 expm's, extract blocks ------------
__global__ void s2_kernel(const float* __restrict__ lin) {
    __shared__ float2 Rb[1296], Tb[1296];
    __shared__ float2 h1[36], h2[36];
    __shared__ int r1[36], r2[36];
    int gid = blockIdx.x;          // hl*10 + g
    int l = gid / 20, rem = gid % 20, half = rem / 10, g = rem % 10;
    const float* p = lin + l * 63 + (half ? 29 : 0);
    float theta = p[g], phi = p[10 + g];
    float sp, cp; sincosf(phi, &sp, &cp);
    int tid = threadIdx.x;
    if (tid < 36) {
        int i1 = tid / 6, i2 = tid % 6;
        if (i1 + 1 < 6 && i2 - 1 >= 0) {
            float v = theta * sqrtf((float)((i1 + 1) * i2)) * (1.f / 64.f);
            h1[tid] = make_float2(v * cp, v * sp); r1[tid] = (i1 + 1) * 6 + (i2 - 1);
        } else { h1[tid] = make_float2(0.f, 0.f); r1[tid] = tid; }
        if (i1 - 1 >= 0 && i2 + 1 < 6) {
            float v = theta * sqrtf((float)(i1 * (i2 + 1))) * (1.f / 64.f);
            h2[tid] = make_float2(-v * cp, v * sp); r2[tid] = (i1 - 1) * 6 + (i2 + 1);
        } else { h2[tid] = make_float2(0.f, 0.f); r2[tid] = tid; }
    }
    for (int e = tid; e < 1296; e += blockDim.x) {
        int row = e / 36, col = e % 36;
        Rb[e] = make_float2((row == col) ? 1.f : 0.f, 0.f);
    }
    __syncthreads();
    for (int k = 16; k >= 1; k--) {
        for (int e = tid; e < 1296; e += blockDim.x) {
            int row = e / 36, col = e % 36;
            float2 acc = make_float2(0.f, 0.f);
            acc = cmadd(h1[row], Rb[r1[row] * 36 + col], acc);
            acc = cmadd(h2[row], Rb[r2[row] * 36 + col], acc);
            Tb[e] = acc;
        }
        __syncthreads();
        float inv = 1.f / (float)k;
        for (int e = tid; e < 1296; e += blockDim.x) {
            int row = e / 36, col = e % 36;
            float d = (row == col) ? 1.f : 0.f;
            Rb[e] = make_float2(fmaf(Tb[e].x, inv, d), Tb[e].y * inv);
        }
        __syncthreads();
    }
    float2* cur = Rb; float2* nxt = Tb;
    for (int s = 0; s < 6; s++) {
        for (int e = tid; e < 1296; e += blockDim.x) {
            int row = e / 36, col = e % 36;
            float2 acc = make_float2(0.f, 0.f);
#pragma unroll
            for (int kk = 0; kk < 36; kk++)
                acc = cmadd(cur[row * 36 + kk], cur[kk * 36 + col], acc);
            nxt[e] = acc;
        }
        __syncthreads();
        float2* t = cur; cur = nxt; nxt = t;
    }
    // extract block-diagonal entries (total photon number conserved)
    int hl = gid / 10, gg = gid % 10;
    for (int t = tid; t < 146; t += blockDim.x) {
        int off = 0, ss = 0, bsz = 1;
        for (ss = 0; ss < 11; ss++) {
            bsz = (ss < 6) ? ss + 1 : 11 - ss;
            if (t < off + bsz * bsz) break;
            off += bsz * bsz;
        }
        int local = t - off;
        int r = local / bsz, c = local % bsz;
        int lo = (ss < 6) ? 0 : ss - 5;
        int rj = (lo + r) * 6 + (ss - lo - r);
        int cj = (lo + c) * 6 + (ss - lo - c);
        float2 u = cur[rj * 36 + cj];
        g_all[hl * HLSZ + gg * 146 + t] = GU{pack2(u.x), pack2(u.y)};
    }
}

// ---------------- gate applications: natural compile-time strides --------------
template <int K>
__device__ __forceinline__ void apply_bs_T(const GU* __restrict__ U, float2* st, int tid) {
    constexpr int SPv[5] = {1296, 216, 36, 6, 1};
    constexpr int SA = SPv[K], SB = SPv[K + 1];
    constexpr int sm0 = (K == 0) ? 2 : 0;
    constexpr int sm1 = (K <= 1) ? 3 : 1;
    constexpr int sm2 = (K <= 2) ? 4 : 2;
    constexpr int om0 = SPv[sm0], om1 = SPv[sm1], om2 = SPv[sm2];
    if (tid >= 216) return;
    int d0 = tid % 6, t1 = tid / 6;
    int d1 = t1 % 6, d2 = t1 / 6;
    int base = d0 * om2 + d1 * om1 + d2 * om0;
    const ull* sp = (const ull*)st;
    int t = 0;
    // photon-number sectors: <=6 inputs live at a time (no spills)
#pragma unroll
    for (int s = 0; s < 11; s++) {
        const int bsz = (s < 6) ? s + 1 : 11 - s;
        const int lo = (s < 6) ? 0 : s - 5;
        ull in[6];
#pragma unroll
        for (int c = 0; c < bsz; c++)
            in[c] = sp[base + (lo + c) * SA + (s - lo - c) * SB];
#pragma unroll
        for (int r = 0; r < bsz; r++) {
            ull S1 = 0, S2 = 0;
#pragma unroll
            for (int c = 0; c < bsz; c++) {
                GU gg = U[t]; t++;
                ffma2(S1, gg.a, in[c]);
                ffma2(S2, gg.b, in[c]);
            }
            float2 f1 = *(float2*)&S1;
            float2 f2 = *(float2*)&S2;
            st[base + (lo + r) * SA + (s - lo - r) * SB] = make_float2(f1.x - f2.y, f1.y + f2.x);
        }
    }
}

template <int M, bool SQ>
__device__ __forceinline__ void apply_1m_T(const GU* __restrict__ U, float2* st, int tid) {
    constexpr int SPv[5] = {1296, 216, 36, 6, 1};
    constexpr int SM = SPv[M];
    constexpr int a0 = (M == 0) ? 1 : 0;
    constexpr int a1 = (M <= 1) ? 2 : 1;
    constexpr int a2 = (M <= 2) ? 3 : 2;
    constexpr int a3 = (M <= 3) ? 4 : 3;
    constexpr int om0 = SPv[a0], om1 = SPv[a1], om2 = SPv[a2], om3 = SPv[a3];
    for (int f = tid; f < 1296; f += BD) {
        int e0 = f % 6, t = f / 6;
        int e1 = t % 6; t /= 6;
        int e2 = t % 6; int e3 = t / 6;
        int base = e0 * om3 + e1 * om2 + e2 * om1 + e3 * om0;
        const ull* sp = (const ull*)st;
        ull in[6];
#pragma unroll
        for (int q = 0; q < 6; q++) in[q] = sp[base + q * SM];
#pragma unroll
        for (int p = 0; p < 6; p++) {
            ull S1 = 0, S2 = 0;
            if (SQ) {          // squeeze: parity-conserving (p-q even only)
#pragma unroll
                for (int q = (p & 1); q < 6; q += 2) {
                    GU gg = U[p * 6 + q];
                    ffma2(S1, gg.a, in[q]);
                    ffma2(S2, gg.b, in[q]);
                }
            } else {
#pragma unroll
                for (int q = 0; q < 6; q++) {
                    GU gg = U[p * 6 + q];
                    ffma2(S1, gg.a, in[q]);
                    ffma2(S2, gg.b, in[q]);
                }
            }
            float2 f1 = *(float2*)&S1;
            float2 f2 = *(float2*)&S2;
            st[base + p * SM] = make_float2(f1.x - f2.y, f1.y + f2.x);
        }
    }
}

// ---------------- main kernel: one CTA per batch element, occ 3 ---------------
// STEP: prefetch gate k+1's coeffs (LDG before compute), apply gate k, commit STS.
#define STEP(k, APPLY) {                                              \
    GU pre;                                                           \
    const bool doPre = ((k) + 1 < NGATE) && (tid < GSZ((k) + 1));     \
    if (doPre) pre = g_all[GOFF((k) + 1) + tid];                      \
    APPLY;                                                            \
    if (doPre) (((k + 1) & 1) ? bufB : bufA)[tid] = pre;              \
    __syncthreads(); }

#define BUF(k) (((k) & 1) ? bufB : bufA)

#define HALFLAYER(base, SQF) \
    STEP(base + 0,  apply_bs_T<0>(BUF(base + 0), st, tid))            \
    STEP(base + 1,  apply_bs_T<2>(BUF(base + 1), st, tid))            \
    STEP(base + 2,  apply_bs_T<1>(BUF(base + 2), st, tid))            \
    STEP(base + 3,  apply_bs_T<3>(BUF(base + 3), st, tid))            \
    STEP(base + 4,  apply_bs_T<0>(BUF(base + 4), st, tid))            \
    STEP(base + 5,  apply_bs_T<2>(BUF(base + 5), st, tid))            \
    STEP(base + 6,  apply_bs_T<1>(BUF(base + 6), st, tid))            \
    STEP(base + 7,  apply_bs_T<3>(BUF(base + 7), st, tid))            \
    STEP(base + 8,  apply_bs_T<0>(BUF(base + 8), st, tid))            \
    STEP(base + 9,  apply_bs_T<2>(BUF(base + 9), st, tid))            \
    STEP(base + 10, (apply_1m_T<0, SQF>(BUF(base + 10), st, tid)))    \
    STEP(base + 11, (apply_1m_T<1, SQF>(BUF(base + 11), st, tid)))    \
    STEP(base + 12, (apply_1m_T<2, SQF>(BUF(base + 12), st, tid)))    \
    STEP(base + 13, (apply_1m_T<3, SQF>(BUF(base + 13), st, tid)))    \
    STEP(base + 14, (apply_1m_T<4, SQF>(BUF(base + 14), st, tid)))

__global__ void __launch_bounds__(BD, 3) qdn_main(float* __restrict__ out) {
    extern __shared__ __align__(16) char smraw[];
    GU* bufA = (GU*)smraw;                                 // 2336 B
    GU* bufB = (GU*)(smraw + 146 * sizeof(GU));            // 2336 B
    float2* st = (float2*)(smraw + 292 * sizeof(GU));      // 62208 B
    __shared__ float ct[30];
    __shared__ float red[16];

    int b = blockIdx.x;
    int tid = threadIdx.x;

    // ---- stage gate 0 + initial product state (real) ----
    if (tid < 146) bufA[tid] = g_all[tid];
    if (tid < 30) ct[tid] = g_init[(b * 5 + tid / 6) * 6 + (tid % 6)];
    __syncthreads();
    for (int idx = tid; idx < DIM; idx += BD) {
        int t = idx;
        int d4 = t % 6; t /= 6; int d3 = t % 6; t /= 6; int d2 = t % 6; t /= 6;
        int d1 = t % 6; int d0 = t / 6;
        float v = ct[d0] * ct[6 + d1] * ct[12 + d2] * ct[18 + d3] * ct[24 + d4];
        st[idx] = make_float2(v, 0.f);
    }
    __syncthreads();

    // ---- 8 half-layers, fully static schedule with gate-ahead prefetch ----
    HALFLAYER(0,   true)
    HALFLAYER(15,  false)
    HALFLAYER(30,  true)
    HALFLAYER(45,  false)
    HALFLAYER(60,  true)
    HALFLAYER(75,  false)
    HALFLAYER(90,  true)
    HALFLAYER(105, false)

    // ---- expectations <X_0>, <X_1> ----
    float acc0 = 0.f, acc1 = 0.f;
    for (int idx = tid; idx < DIM; idx += BD) {
        int d0 = idx / 1296;
        int d1 = (idx / 216) % 6;
        float2 a = st[idx];
        if (d0 < 5) {
            float2 bb = st[idx + 1296];
            acc0 = fmaf(SQT[d0], a.x * bb.x + a.y * bb.y, acc0);
        }
        if (d1 < 5) {
            float2 bb = st[idx + 216];
            acc1 = fmaf(SQT[d1], a.x * bb.x + a.y * bb.y, acc1);
        }
    }
#pragma unroll
    for (int off = 16; off > 0; off >>= 1) {
        acc0 += __shfl_down_sync(0xffffffffu, acc0, off);
        acc1 += __shfl_down_sync(0xffffffffu, acc1, off);
    }
    int w = tid >> 5, lane = tid & 31;
    if (lane == 0) { red[w] = acc0; red[8 + w] = acc1; }
    __syncthreads();
    if (tid == 0) {
        float s0 = 0.f, s1 = 0.f;
        for (int ww = 0; ww < 8; ww++) { s0 += red[ww]; s1 += red[8 + ww]; }
        out[b * 2 + 0] = 2.f * s0;
        out[b * 2 + 1] = 2.f * s1;
    }
}

// ---------------- launch ----------------
extern "C" void kernel_launch(void* const* d_in, const int* in_sizes, int n_in,
                              void* d_out, int out_size) {
    const float* x    = (const float*)d_in[0];
    const float* lin  = (const float*)d_in[1];
    const float* act  = (const float*)d_in[2];
    const float* lact = (const float*)d_in[3];
    float* out = (float*)d_out;
    int B = in_sizes[0] / 5;

    size_t shm = 292 * sizeof(GU) + (size_t)DIM * sizeof(float2);   // 66880 B
    cudaFuncSetAttribute(qdn_main, cudaFuncAttributeMaxDynamicSharedMemorySize, (int)shm);

    int n1 = B * 5 + 40;
    noop_kernel<<<1, 32>>>();
    s1_kernel<<<(n1 + 255) / 256, 256>>>(x, lin, act, lact, B);
    s2_kernel<<<80, 256>>>(lin);
    qdn_main<<<B, BD, shm>>>(out);
}

// round 10
// speedup vs baseline: 1.9494x; 1.9494x over previous
#include <cuda_runtime.h>
#include <math.h>

// C=6, N=5 modes, LAYERS=4, OUTPUT=2, B=2048
#define DIM 7776            // 6^5
#define BD  256
typedef unsigned long long ull;

// Half-layer gate storage (plain complex float2):
//   10 BS gates x 164 (sector rows padded to even length) = 1640
//   5 one-mode gates x 36 (squeeze compacted to 24 used)  = 180
#define HLF2 1820
#define HLF4 910

// ---------------- persistent device scratch ----------------
__device__ __align__(16) float2 g_all[8 * HLF2];   // all gates, execution order
__device__ float g_init[2048 * 5 * 6];

__constant__ float SQT[5] = {1.0f, 1.41421356237f, 1.73205080757f, 2.0f, 2.2360679775f};

// ---------------- helpers ----------------
__device__ __forceinline__ float2 cmul(float2 a, float2 b) {
    return make_float2(a.x * b.x - a.y * b.y, a.x * b.y + a.y * b.x);
}
__device__ __forceinline__ float2 cmadd(float2 a, float2 b, float2 c) {
    c.x = fmaf(a.x, b.x, fmaf(-a.y, b.y, c.x));
    c.y = fmaf(a.x, b.y, fmaf(a.y, b.x, c.y));
    return c;
}
__device__ __forceinline__ void ffma2(ull& d, ull a, ull b) {
    asm("fma.rn.f32x2 %0, %1, %2, %0;" : "+l"(d) : "l"(a), "l"(b));
}
// from packed complex v=(re,im) build dR=(re,re), dI=(im,im)
__device__ __forceinline__ void dupRI(ull v, ull& dR, ull& dI) {
    unsigned lo, hi;
    asm("mov.b64 {%0,%1}, %2;" : "=r"(lo), "=r"(hi) : "l"(v));
    asm("mov.b64 %0, {%1,%1};" : "=l"(dR) : "r"(lo));
    asm("mov.b64 %0, {%1,%1};" : "=l"(dI) : "r"(hi));
}

// ---------------- banded 6x6 expm (registers), bands at +-D, pre-scaled 1/64 ----
template <int D>
__device__ void expm_banded(const float2* lo, const float2* hi, float2* R) {
    float2 T[36];
#pragma unroll
    for (int i = 0; i < 36; i++) R[i] = make_float2(((i % 6) == (i / 6)) ? 1.f : 0.f, 0.f);
#pragma unroll 1
    for (int k = 16; k >= 1; k--) {
#pragma unroll
        for (int i = 0; i < 6; i++) {
#pragma unroll
            for (int j = 0; j < 6; j++) {
                float2 acc = make_float2(0.f, 0.f);
                if (i >= D)    acc = cmadd(lo[i], R[(i - D) * 6 + j], acc);
                if (i + D < 6) acc = cmadd(hi[i], R[(i + D) * 6 + j], acc);
                T[i * 6 + j] = acc;
            }
        }
        float inv = 1.f / (float)k;
#pragma unroll
        for (int i = 0; i < 36; i++) {
            float d = ((i % 6) == (i / 6)) ? 1.f : 0.f;
            R[i] = make_float2(fmaf(T[i].x, inv, d), T[i].y * inv);
        }
    }
#pragma unroll 1
    for (int s = 0; s < 6; s++) {
#pragma unroll
        for (int i = 0; i < 6; i++)
#pragma unroll
            for (int j = 0; j < 6; j++) {
                float2 acc = make_float2(0.f, 0.f);
#pragma unroll
                for (int kk = 0; kk < 6; kk++) acc = cmadd(R[i * 6 + kk], R[kk * 6 + j], acc);
                T[i * 6 + j] = acc;
            }
#pragma unroll
        for (int i = 0; i < 36; i++) R[i] = T[i];
    }
}

// ---------------- dummy kernel (ncu launch-index alignment) ----------------
__global__ void noop_kernel() {}

// ---------------- S1: initial columns + 6x6 gates (rot + kerr folded) ----------
__global__ void s1_kernel(const float* __restrict__ x, const float* __restrict__ lin,
                          const float* __restrict__ act, const float* __restrict__ lact,
                          int B) {
    int idx = blockIdx.x * blockDim.x + threadIdx.x;
    int nInit = B * 5;
    const float sc = 1.f / 64.f;
    float2 lo[6], hi[6], R[36];
    if (idx < nInit) {
        float r = x[idx];   // disp(r, 0)
#pragma unroll
        for (int n = 0; n < 6; n++) {
            lo[n] = make_float2(r * sqrtf((float)n) * sc, 0.f);
            hi[n] = make_float2(-r * sqrtf((float)(n + 1)) * sc, 0.f);
        }
        expm_banded<1>(lo, hi, R);
#pragma unroll
        for (int n = 0; n < 6; n++) g_init[idx * 6 + n] = R[n * 6].x;  // column 0 (real)
    } else if (idx < nInit + 40) {
        int k = idx - nInit;
        int isDp = (k >= 20);
        int k2 = isDp ? k - 20 : k;
        int l = k2 / 5, i = k2 - 5 * l;
        float rphi;
        if (!isDp) {
            float r = lin[l * 63 + 24 + i];
#pragma unroll
            for (int n = 0; n < 6; n++) {
                lo[n] = make_float2(-0.5f * r * sqrtf((float)(n * (n - 1))) * sc, 0.f);
                hi[n] = make_float2( 0.5f * r * sqrtf((float)((n + 1) * (n + 2))) * sc, 0.f);
            }
            expm_banded<2>(lo, hi, R);
            rphi = (i < 4) ? lin[l * 63 + 20 + i] : 0.f;   // interferometer A rot
        } else {
            float dr = lin[l * 63 + 53 + i];
            float dp = lin[l * 63 + 58 + i];
            float sp, cp; sincosf(dp, &sp, &cp);
#pragma unroll
            for (int n = 0; n < 6; n++) {
                float sn = sqrtf((float)n) * sc, sn1 = sqrtf((float)(n + 1)) * sc;
                lo[n] = make_float2(dr * cp * sn, dr * sp * sn);
                hi[n] = make_float2(-dr * cp * sn1, dr * sp * sn1);
            }
            expm_banded<1>(lo, hi, R);
            rphi = (i < 4) ? lin[l * 63 + 49 + i] : 0.f;   // interferometer B rot
        }
        // fold rotation diagonal: column j *= e^{i rphi j}
#pragma unroll
        for (int c = 0; c < 6; c++) {
            float s2, c2; sincosf(rphi * (float)c, &s2, &c2);
            float2 ph = make_float2(c2, s2);
#pragma unroll
            for (int rr = 0; rr < 6; rr++) R[rr * 6 + c] = cmul(R[rr * 6 + c], ph);
        }
        if (isDp) {
            // fold kerr diagonal (applied right after disp on same mode): row r *= e^{i kv r^2}
            float kv = (l < 3) ? act[l * 5 + i] : ((i < 2) ? lact[i] : 0.f);
#pragma unroll
            for (int rr = 0; rr < 6; rr++) {
                float s2, c2; sincosf(kv * (float)(rr * rr), &s2, &c2);
                float2 ph = make_float2(c2, s2);
#pragma unroll
                for (int c = 0; c < 6; c++) R[rr * 6 + c] = cmul(ph, R[rr * 6 + c]);
            }
        }
        int hl = 2 * l + (isDp ? 1 : 0);
        float2* dst = g_all + hl * HLF2 + 1640 + i * 36;
        if (!isDp) {
            // squeeze: compact parity-sparse rows: row p holds q = (p&1)+2j, j=0..2, + pad
#pragma unroll
            for (int p = 0; p < 6; p++) {
#pragma unroll
                for (int j = 0; j < 3; j++) dst[p * 4 + j] = R[p * 6 + (p & 1) + 2 * j];
                dst[p * 4 + 3] = make_float2(0.f, 0.f);
            }
        } else {
#pragma unroll
            for (int e = 0; e < 36; e++) dst[e] = R[e];
        }
    }
}

// ---------------- S2: 80 beam-splitter 36x36 expm's, padded block extraction ----
__global__ void s2_kernel(const float* __restrict__ lin) {
    __shared__ float2 Rb[1296], Tb[1296];
    __shared__ float2 h1[36], h2[36];
    __shared__ int r1[36], r2[36];
    int gid = blockIdx.x;          // hl*10 + g
    int l = gid / 20, rem = gid % 20, half = rem / 10, g = rem % 10;
    const float* p = lin + l * 63 + (half ? 29 : 0);
    float theta = p[g], phi = p[10 + g];
    float sp, cp; sincosf(phi, &sp, &cp);
    int tid = threadIdx.x;
    if (tid < 36) {
        int i1 = tid / 6, i2 = tid % 6;
        if (i1 + 1 < 6 && i2 - 1 >= 0) {
            float v = theta * sqrtf((float)((i1 + 1) * i2)) * (1.f / 64.f);
            h1[tid] = make_float2(v * cp, v * sp); r1[tid] = (i1 + 1) * 6 + (i2 - 1);
        } else { h1[tid] = make_float2(0.f, 0.f); r1[tid] = tid; }
        if (i1 - 1 >= 0 && i2 + 1 < 6) {
            float v = theta * sqrtf((float)(i1 * (i2 + 1))) * (1.f / 64.f);
            h2[tid] = make_float2(-v * cp, v * sp); r2[tid] = (i1 - 1) * 6 + (i2 + 1);
        } else { h2[tid] = make_float2(0.f, 0.f); r2[tid] = tid; }
    }
    for (int e = tid; e < 1296; e += blockDim.x) {
        int row = e / 36, col = e % 36;
        Rb[e] = make_float2((row == col) ? 1.f : 0.f, 0.f);
    }
    __syncthreads();
    for (int k = 16; k >= 1; k--) {
        for (int e = tid; e < 1296; e += blockDim.x) {
            int row = e / 36, col = e % 36;
            float2 acc = make_float2(0.f, 0.f);
            acc = cmadd(h1[row], Rb[r1[row] * 36 + col], acc);
            acc = cmadd(h2[row], Rb[r2[row] * 36 + col], acc);
            Tb[e] = acc;
        }
        __syncthreads();
        float inv = 1.f / (float)k;
        for (int e = tid; e < 1296; e += blockDim.x) {
            int row = e / 36, col = e % 36;
            float d = (row == col) ? 1.f : 0.f;
            Rb[e] = make_float2(fmaf(Tb[e].x, inv, d), Tb[e].y * inv);
        }
        __syncthreads();
    }
    float2* cur = Rb; float2* nxt = Tb;
    for (int s = 0; s < 6; s++) {
        for (int e = tid; e < 1296; e += blockDim.x) {
            int row = e / 36, col = e % 36;
            float2 acc = make_float2(0.f, 0.f);
#pragma unroll
            for (int kk = 0; kk < 36; kk++)
                acc = cmadd(cur[row * 36 + kk], cur[kk * 36 + col], acc);
            nxt[e] = acc;
        }
        __syncthreads();
        float2* t = cur; cur = nxt; nxt = t;
    }
    // write block-diagonal entries in padded-even-row layout (164 slots/gate)
    int hl = gid / 10, gg = gid % 10;
    for (int slot = tid; slot < 164; slot += blockDim.x) {
        int off = 0, s = 0, bsz = 1, bszP = 2;
        for (s = 0; s < 11; s++) {
            bsz = (s < 6) ? s + 1 : 11 - s;
            bszP = (bsz + 1) & ~1;
            if (slot < off + bsz * bszP) break;
            off += bsz * bszP;
        }
        int local = slot - off;
        int r = local / bszP, c = local % bszP;
        float2 v = make_float2(0.f, 0.f);
        if (c < bsz) {
            int lo = (s < 6) ? 0 : s - 5;
            int rj = (lo + r) * 6 + (s - lo - r);
            int cj = (lo + c) * 6 + (s - lo - c);
            v = cur[rj * 36 + cj];
        }
        g_all[hl * HLF2 + gg * 164 + slot] = v;
    }
}

// ---------------- gate applications: paired gate loads + dup'd state -----------
template <int K>
__device__ __forceinline__ void apply_bs_T(const float2* __restrict__ Uf, float2* st, int tid) {
    constexpr int SPv[5] = {1296, 216, 36, 6, 1};
    constexpr int SA = SPv[K], SB = SPv[K + 1];
    constexpr int sm0 = (K == 0) ? 2 : 0;
    constexpr int sm1 = (K <= 1) ? 3 : 1;
    constexpr int sm2 = (K <= 2) ? 4 : 2;
    constexpr int om0 = SPv[sm0], om1 = SPv[sm1], om2 = SPv[sm2];
    if (tid >= 216) return;
    int d0 = tid % 6, t1 = tid / 6;
    int d1 = t1 % 6, d2 = t1 / 6;
    int base = d0 * om2 + d1 * om1 + d2 * om0;
    const ull* sp = (const ull*)st;
    const ulonglong2* Up = (const ulonglong2*)Uf;
    constexpr int secF4[11] = {0, 1, 3, 9, 17, 32, 50, 65, 73, 79, 81};
#pragma unroll
    for (int s = 0; s < 11; s++) {
        const int bsz = (s < 6) ? s + 1 : 11 - s;
        const int lo = (s < 6) ? 0 : s - 5;
        const int bszP2 = (bsz + 1) / 2;          // float4 per row
        ull dR[6], dI[6];
#pragma unroll
        for (int c = 0; c < bsz; c++) {
            ull v = sp[base + (lo + c) * SA + (s - lo - c) * SB];
            dupRI(v, dR[c], dI[c]);
        }
        if (bsz & 1) { dR[bsz] = 0; dI[bsz] = 0; }   // pad slot (coeff stored 0)
#pragma unroll
        for (int r = 0; r < bsz; r++) {
            ull S1 = 0, S2 = 0;
#pragma unroll
            for (int cp = 0; cp < bszP2; cp++) {
                ulonglong2 gg = Up[secF4[s] + r * bszP2 + cp];
                ffma2(S1, gg.x, dR[2 * cp]);     ffma2(S2, gg.x, dI[2 * cp]);
                ffma2(S1, gg.y, dR[2 * cp + 1]); ffma2(S2, gg.y, dI[2 * cp + 1]);
            }
            float2 f1 = *(float2*)&S1;
            float2 f2 = *(float2*)&S2;
            st[base + (lo + r) * SA + (s - lo - r) * SB] = make_float2(f1.x - f2.y, f1.y + f2.x);
        }
    }
}

template <int M, bool SQ>
__device__ __forceinline__ void apply_1m_T(const float2* __restrict__ Uf, float2* st, int tid) {
    constexpr int SPv[5] = {1296, 216, 36, 6, 1};
    constexpr int SM = SPv[M];
    constexpr int a0 = (M == 0) ? 1 : 0;
    constexpr int a1 = (M <= 1) ? 2 : 1;
    constexpr int a2 = (M <= 2) ? 3 : 2;
    constexpr int a3 = (M <= 3) ? 4 : 3;
    constexpr int om0 = SPv[a0], om1 = SPv[a1], om2 = SPv[a2], om3 = SPv[a3];
    const ulonglong2* Up = (const ulonglong2*)Uf;
    for (int f = tid; f < 1296; f += BD) {
        int e0 = f % 6, t = f / 6;
        int e1 = t % 6; t /= 6;
        int e2 = t % 6; int e3 = t / 6;
        int base = e0 * om3 + e1 * om2 + e2 * om1 + e3 * om0;
        const ull* sp = (const ull*)st;
        ull dR[6], dI[6];
#pragma unroll
        for (int q = 0; q < 6; q++) dupRI(sp[base + q * SM], dR[q], dI[q]);
#pragma unroll
        for (int p = 0; p < 6; p++) {
            ull S1 = 0, S2 = 0;
            if (SQ) {           // compact parity rows: q = (p&1)+2j, j<3, + zero pad
                const int q0 = p & 1;
                ulonglong2 g0 = Up[p * 2 + 0];
                ulonglong2 g1 = Up[p * 2 + 1];
                ffma2(S1, g0.x, dR[q0]);     ffma2(S2, g0.x, dI[q0]);
                ffma2(S1, g0.y, dR[q0 + 2]); ffma2(S2, g0.y, dI[q0 + 2]);
                ffma2(S1, g1.x, dR[q0 + 4]); ffma2(S2, g1.x, dI[q0 + 4]);
                // g1.y is the stored-zero pad: contributes 0
                ffma2(S1, g1.y, dR[q0]);     ffma2(S2, g1.y, dI[q0]);
            } else {
#pragma unroll
                for (int cp = 0; cp < 3; cp++) {
                    ulonglong2 gg = Up[p * 3 + cp];
                    ffma2(S1, gg.x, dR[2 * cp]);     ffma2(S2, gg.x, dI[2 * cp]);
                    ffma2(S1, gg.y, dR[2 * cp + 1]); ffma2(S2, gg.y, dI[2 * cp + 1]);
                }
            }
            float2 f1 = *(float2*)&S1;
            float2 f2 = *(float2*)&S2;
            st[base + p * SM] = make_float2(f1.x - f2.y, f1.y + f2.x);
        }
    }
}

// ---------------- main kernel: one CTA per batch element, occ 2 ---------------
__global__ void __launch_bounds__(BD, 2) qdn_main(float* __restrict__ out) {
    extern __shared__ __align__(16) char smraw[];
    float2* Ustage = (float2*)smraw;                        // 14560 B
    float2* st = (float2*)(smraw + HLF2 * sizeof(float2));  // 62208 B
    __shared__ float ct[30];
    __shared__ float red[16];

    int b = blockIdx.x;
    int tid = threadIdx.x;

    // ---- initial product state (real) ----
    if (tid < 30) ct[tid] = g_init[(b * 5 + tid / 6) * 6 + (tid % 6)];
    __syncthreads();
    for (int idx = tid; idx < DIM; idx += BD) {
        int t = idx;
        int d4 = t % 6; t /= 6; int d3 = t % 6; t /= 6; int d2 = t % 6; t /= 6;
        int d1 = t % 6; int d0 = t / 6;
        float v = ct[d0] * ct[6 + d1] * ct[12 + d2] * ct[18 + d3] * ct[24 + d4];
        st[idx] = make_float2(v, 0.f);
    }
    __syncthreads();

    for (int l = 0; l < 4; l++) {
        for (int half = 0; half < 2; half++) {
            // stage this half-layer's gates (float4 bulk copy)
            const float4* srcU = (const float4*)(g_all + (l * 2 + half) * HLF2);
            float4* dstU = (float4*)Ustage;
            for (int i = tid; i < HLF4; i += BD) dstU[i] = srcU[i];
            __syncthreads();
            // BS gate mode sequence: 0,2,1,3,0,2,1,3,0,2
            apply_bs_T<0>(Ustage + 0 * 164, st, tid); __syncthreads();
            apply_bs_T<2>(Ustage + 1 * 164, st, tid); __syncthreads();
            apply_bs_T<1>(Ustage + 2 * 164, st, tid); __syncthreads();
            apply_bs_T<3>(Ustage + 3 * 164, st, tid); __syncthreads();
            apply_bs_T<0>(Ustage + 4 * 164, st, tid); __syncthreads();
            apply_bs_T<2>(Ustage + 5 * 164, st, tid); __syncthreads();
            apply_bs_T<1>(Ustage + 6 * 164, st, tid); __syncthreads();
            apply_bs_T<3>(Ustage + 7 * 164, st, tid); __syncthreads();
            apply_bs_T<0>(Ustage + 8 * 164, st, tid); __syncthreads();
            apply_bs_T<2>(Ustage + 9 * 164, st, tid); __syncthreads();
            if (half == 0) {   // squeeze gates: compact parity rows
                apply_1m_T<0, true>(Ustage + 1640 + 0 * 36, st, tid); __syncthreads();
                apply_1m_T<1, true>(Ustage + 1640 + 1 * 36, st, tid); __syncthreads();
                apply_1m_T<2, true>(Ustage + 1640 + 2 * 36, st, tid); __syncthreads();
                apply_1m_T<3, true>(Ustage + 1640 + 3 * 36, st, tid); __syncthreads();
                apply_1m_T<4, true>(Ustage + 1640 + 4 * 36, st, tid); __syncthreads();
            } else {           // displacement gates (rot+kerr folded): dense
                apply_1m_T<0, false>(Ustage + 1640 + 0 * 36, st, tid); __syncthreads();
                apply_1m_T<1, false>(Ustage + 1640 + 1 * 36, st, tid); __syncthreads();
                apply_1m_T<2, false>(Ustage + 1640 + 2 * 36, st, tid); __syncthreads();
                apply_1m_T<3, false>(Ustage + 1640 + 3 * 36, st, tid); __syncthreads();
                apply_1m_T<4, false>(Ustage + 1640 + 4 * 36, st, tid); __syncthreads();
            }
        }
    }

    // ---- expectations <X_0>, <X_1> ----
    float acc0 = 0.f, acc1 = 0.f;
    for (int idx = tid; idx < DIM; idx += BD) {
        int d0 = idx / 1296;
        int d1 = (idx / 216) % 6;
        float2 a = st[idx];
        if (d0 < 5) {
            float2 bb = st[idx + 1296];
            acc0 = fmaf(SQT[d0], a.x * bb.x + a.y * bb.y, acc0);
        }
        if (d1 < 5) {
            float2 bb = st[idx + 216];
            acc1 = fmaf(SQT[d1], a.x * bb.x + a.y * bb.y, acc1);
        }
    }
#pragma unroll
    for (int off = 16; off > 0; off >>= 1) {
        acc0 += __shfl_down_sync(0xffffffffu, acc0, off);
        acc1 += __shfl_down_sync(0xffffffffu, acc1, off);
    }
    int w = tid >> 5, lane = tid & 31;
    if (lane == 0) { red[w] = acc0; red[8 + w] = acc1; }
    __syncthreads();
    if (tid == 0) {
        float s0 = 0.f, s1 = 0.f;
        for (int ww = 0; ww < 8; ww++) { s0 += red[ww]; s1 += red[8 + ww]; }
        out[b * 2 + 0] = 2.f * s0;
        out[b * 2 + 1] = 2.f * s1;
    }
}

// ---------------- launch ----------------
extern "C" void kernel_launch(void* const* d_in, const int* in_sizes, int n_in,
                              void* d_out, int out_size) {
    const float* x    = (const float*)d_in[0];
    const float* lin  = (const float*)d_in[1];
    const float* act  = (const float*)d_in[2];
    const float* lact = (const float*)d_in[3];
    float* out = (float*)d_out;
    int B = in_sizes[0] / 5;

    size_t shm = HLF2 * sizeof(float2) + (size_t)DIM * sizeof(float2);   // 76768 B
    cudaFuncSetAttribute(qdn_main, cudaFuncAttributeMaxDynamicSharedMemorySize, (int)shm);

    int n1 = B * 5 + 40;
    noop_kernel<<<1, 32>>>();
    s1_kernel<<<(n1 + 255) / 256, 256>>>(x, lin, act, lact, B);
    s2_kernel<<<80, 256>>>(lin);
    qdn_main<<<B, BD, shm>>>(out);
}